// round 17
// baseline (speedup 1.0000x reference)
#include <cuda_runtime.h>
#include <math.h>

// ---- DCT basis as compile-time immediates (truncated-pi basis, <4e-7 err) --
#define P0 0.35355339059327373f
#define P1 0.4903926402016152f
#define P2 0.46193976625564337f
#define P3 0.4157348061512726f
#define P4 0.3535533905932738f
#define P5 0.2777851165098011f
#define P6 0.1913417161825449f
#define P7 0.09754516100806412f

// dst = C * src, butterfly form (even rows symmetric, odd rows antisymmetric)
#define MUL_ROWS(dst, src) do { \
    float s0=(src)[0]+(src)[7], s1=(src)[1]+(src)[6], s2=(src)[2]+(src)[5], s3=(src)[3]+(src)[4]; \
    float d0=(src)[0]-(src)[7], d1=(src)[1]-(src)[6], d2=(src)[2]-(src)[5], d3=(src)[3]-(src)[4]; \
    float ea=s0+s3, eb=s1+s2, ec=s0-s3, ed=s1-s2; \
    (dst)[0]=P0*(ea+eb); \
    (dst)[4]=P4*(ea-eb); \
    (dst)[2]=fmaf(P6,ed,P2*ec); \
    (dst)[6]=fmaf(-P2,ed,P6*ec); \
    (dst)[1]=fmaf(P7,d3,fmaf(P5,d2,fmaf(P3,d1,P1*d0))); \
    (dst)[3]=fmaf(-P5,d3,fmaf(-P1,d2,fmaf(-P7,d1,P3*d0))); \
    (dst)[5]=fmaf(P3,d3,fmaf(P7,d2,fmaf(-P1,d1,P5*d0))); \
    (dst)[7]=fmaf(-P1,d3,fmaf(P3,d2,fmaf(-P5,d1,P7*d0))); \
} while (0)

// dst = C^T * src, butterfly form (dst[i]=E_i+O_i, dst[7-i]=E_i-O_i)
#define MUL_COLS(dst, src) do { \
    float t0=P0*(src)[0], u4=P4*(src)[4]; \
    float ps=t0+u4, ms=t0-u4; \
    float E0=fmaf(P6,(src)[6],fmaf( P2,(src)[2],ps)); \
    float E1=fmaf(-P2,(src)[6],fmaf( P6,(src)[2],ms)); \
    float E2=fmaf( P2,(src)[6],fmaf(-P6,(src)[2],ms)); \
    float E3=fmaf(-P6,(src)[6],fmaf(-P2,(src)[2],ps)); \
    float O0=fmaf(P7,(src)[7],fmaf( P5,(src)[5],fmaf( P3,(src)[3],P1*(src)[1]))); \
    float O1=fmaf(-P5,(src)[7],fmaf(-P1,(src)[5],fmaf(-P7,(src)[3],P3*(src)[1]))); \
    float O2=fmaf( P3,(src)[7],fmaf( P7,(src)[5],fmaf(-P1,(src)[3],P5*(src)[1]))); \
    float O3=fmaf(-P1,(src)[7],fmaf( P3,(src)[5],fmaf(-P5,(src)[3],P7*(src)[1]))); \
    (dst)[0]=E0+O0; (dst)[7]=E0-O0; \
    (dst)[1]=E1+O1; (dst)[6]=E1-O1; \
    (dst)[2]=E2+O2; (dst)[5]=E2-O2; \
    (dst)[3]=E3+O3; (dst)[4]=E3-O3; \
} while (0)

// learned mask, COLUMN-major: g_Mc[c*8 + i] = M[i][c]
static __device__ float g_Mc[64];

// Single-warp prep: no block barriers, independent weight loads hoistable.
__global__ void prep_kernel(const float* __restrict__ noise,
                            const float* __restrict__ qmat,
                            const float* __restrict__ qmw,
                            const float* __restrict__ w1, const float* __restrict__ b1,
                            const float* __restrict__ w2, const float* __restrict__ b2,
                            const float* __restrict__ w3, const float* __restrict__ b3)
{
    const unsigned FULL = 0xffffffffu;
    const float inv_sqrt2 = 0.7071067811865476f;
    int lane = threadIdx.x;   // 32 threads

    float h1 = 0.f;
    if (lane < 16) {
        float z = fmaf(noise[0], w1[lane], b1[lane]);
        h1 = 0.5f * z * (1.0f + erff(z * inv_sqrt2));
    }
    float h2 = 0.f;
    {
        float z = (lane < 16) ? b2[lane] : 0.f;
        #pragma unroll
        for (int k = 0; k < 16; k++) {
            float hk = __shfl_sync(FULL, h1, k);
            if (lane < 16) z = fmaf(hk, w2[k * 16 + lane], z);
        }
        if (lane < 16) h2 = 0.5f * z * (1.0f + erff(z * inv_sqrt2));
    }
    float nr = 0.f;
    {
        float z = (lane < 18) ? b3[lane] : 0.f;
        #pragma unroll
        for (int k = 0; k < 16; k++) {
            float hk = __shfl_sync(FULL, h2, k);
            if (lane < 18) z = fmaf(hk, w3[k * 18 + lane], z);
        }
        nr = z;
    }
    float nr0 = __shfl_sync(FULL, nr, 0);
    float nr1 = __shfl_sync(FULL, nr, 1);
    float q = (lane < 16) ? qmw[lane] : -1e30f;
    float m = q;
    #pragma unroll
    for (int d = 8; d >= 1; d >>= 1) m = fmaxf(m, __shfl_xor_sync(FULL, m, d));
    float e = (lane < 16) ? expf(q - m) : 0.f;
    float s = e;
    #pragma unroll
    for (int d = 8; d >= 1; d >>= 1) s += __shfl_xor_sync(FULL, s, d);
    float nr2i = __shfl_sync(FULL, nr, (lane < 16) ? (lane + 2) : 0);
    float coef = (lane < 16) ? (e / s * nr0 + nr1) * nr2i : 0.f;
    int t0 = lane, t1 = lane + 32;
    int i0 = t0 & 7, c0 = t0 >> 3;
    int i1 = t1 & 7, c1 = t1 >> 3;
    float s0 = 0.f, s1 = 0.f;
    #pragma unroll
    for (int k = 0; k < 16; k++) {
        float ck = __shfl_sync(FULL, coef, k);
        s0 = fmaf(ck, qmat[k * 64 + i0 * 8 + c0], s0);
        s1 = fmaf(ck, qmat[k * 64 + i1 * 8 + c1], s1);
    }
    g_Mc[t0] = s0;
    g_Mc[t1] = s1;
}

// 2 lanes per 8x8 block; lane parity p owns rows [4p,4p+4).
// X stashed in smem after S1 (A[32] only persistent state, 64-reg cap,
// 4 CTAs/SM). Mask fetched AFTER grid-dependency sync (PDL overlap with
// prep_kernel). low = C^T((C X C^T).*M)C ; high = X - low. x read once.
__global__ __launch_bounds__(256, 4) void dct_main(const float* __restrict__ x,
                                                   float* __restrict__ lo,
                                                   float* __restrict__ hi)
{
    __shared__ __align__(16) float Ms[64];         // col-major mask (256 B)
    __shared__ float4 xb[8][2][32];                // 8 KB exchange buffer
    __shared__ float4 xs[8][256];                  // 32 KB X stash

    int tid  = threadIdx.x;
    int wid  = tid >> 5;
    int lane = tid & 31;

    int p   = tid & 1;                     // half-block owner
    int g   = blockIdx.x * 128 + (tid >> 1);   // global 8x8-block id
    int img = g >> 6;
    int blk = g & 63;
    int base = (img << 12) + ((blk >> 3) << 9) + ((blk & 7) << 3);
    int r0   = p << 2;                     // first owned row

    // Load X rows, run S1 row-by-row, stash X into smem, keep only A.
    const float* xp = x + base + (r0 << 6);
    float A[32];
    #pragma unroll
    for (int i = 0; i < 4; i++) {
        float4 a = *reinterpret_cast<const float4*>(xp + (i << 6));
        float4 b = *reinterpret_cast<const float4*>(xp + (i << 6) + 4);
        float r[8] = {a.x, a.y, a.z, a.w, b.x, b.y, b.z, b.w};
        MUL_ROWS(&A[i*8], r);              // S1: spectrum row r0+i (partial)
        xs[2*i][tid]   = a;                // stash X row for S4
        xs[2*i+1][tid] = b;
    }

    // T1: quadrant exchange with peer lane (lane^1), two rounds of 2 rows
    #pragma unroll
    for (int h = 0; h < 2; h++) {
        #pragma unroll
        for (int i2 = 0; i2 < 2; i2++) {
            int i = h*2 + i2;
            float4 s = p ? make_float4(A[i*8+0], A[i*8+1], A[i*8+2], A[i*8+3])
                         : make_float4(A[i*8+4], A[i*8+5], A[i*8+6], A[i*8+7]);
            xb[wid][i2][lane] = s;
        }
        __syncwarp();
        #pragma unroll
        for (int i2 = 0; i2 < 2; i2++) {
            int i = h*2 + i2;
            float4 r = xb[wid][i2][lane ^ 1];
            if (p) { A[i*8+0]=r.x; A[i*8+1]=r.y; A[i*8+2]=r.z; A[i*8+3]=r.w; }
            else   { A[i*8+4]=r.x; A[i*8+5]=r.y; A[i*8+6]=r.z; A[i*8+7]=r.w; }
        }
        __syncwarp();
    }

    // Prep result needed from here on: wait for prep_kernel (PDL), load mask.
    cudaGridDependencySynchronize();
    if (tid < 64) Ms[tid] = g_Mc[tid];
    __syncthreads();

    // S2+mask+S3 per owned column c = r0+j (in place in A)
    #pragma unroll
    for (int j = 0; j < 4; j++) {
        float v[8], w[8], z[8];
        #pragma unroll
        for (int i = 0; i < 4; i++) { v[i] = A[i*8+j]; v[4+i] = A[i*8+4+j]; }
        MUL_ROWS(w, v);                    // spectrum column
        const float4 m0 = *reinterpret_cast<const float4*>(&Ms[(r0+j) << 3]);
        const float4 m1 = *reinterpret_cast<const float4*>(&Ms[((r0+j) << 3) + 4]);
        w[0]*=m0.x; w[1]*=m0.y; w[2]*=m0.z; w[3]*=m0.w;
        w[4]*=m1.x; w[5]*=m1.y; w[6]*=m1.z; w[7]*=m1.w;
        MUL_COLS(z, w);                    // Z column
        #pragma unroll
        for (int i = 0; i < 4; i++) { A[i*8+j] = z[i]; A[i*8+4+j] = z[4+i]; }
    }

    // T2: identical quadrant exchange
    #pragma unroll
    for (int h = 0; h < 2; h++) {
        #pragma unroll
        for (int i2 = 0; i2 < 2; i2++) {
            int i = h*2 + i2;
            float4 s = p ? make_float4(A[i*8+0], A[i*8+1], A[i*8+2], A[i*8+3])
                         : make_float4(A[i*8+4], A[i*8+5], A[i*8+6], A[i*8+7]);
            xb[wid][i2][lane] = s;
        }
        __syncwarp();
        #pragma unroll
        for (int i2 = 0; i2 < 2; i2++) {
            int i = h*2 + i2;
            float4 r = xb[wid][i2][lane ^ 1];
            if (p) { A[i*8+0]=r.x; A[i*8+1]=r.y; A[i*8+2]=r.z; A[i*8+3]=r.w; }
            else   { A[i*8+4]=r.x; A[i*8+5]=r.y; A[i*8+6]=r.z; A[i*8+7]=r.w; }
        }
        __syncwarp();
    }

    // S4: low rows = Z*C ; high = (X from smem) - low
    float* lp = lo + base + (r0 << 6);
    float* hp = hi + base + (r0 << 6);
    #pragma unroll
    for (int i = 0; i < 4; i++) {
        float l[8];
        MUL_COLS(l, &A[i*8]);
        float4 a = xs[2*i][tid];
        float4 b = xs[2*i+1][tid];
        *reinterpret_cast<float4*>(lp + (i << 6))     = make_float4(l[0], l[1], l[2], l[3]);
        *reinterpret_cast<float4*>(lp + (i << 6) + 4) = make_float4(l[4], l[5], l[6], l[7]);
        *reinterpret_cast<float4*>(hp + (i << 6)) =
            make_float4(a.x - l[0], a.y - l[1], a.z - l[2], a.w - l[3]);
        *reinterpret_cast<float4*>(hp + (i << 6) + 4) =
            make_float4(b.x - l[4], b.y - l[5], b.z - l[6], b.w - l[7]);
    }
}

extern "C" void kernel_launch(void* const* d_in, const int* in_sizes, int n_in,
                              void* d_out, int out_size)
{
    const float* x     = (const float*)d_in[0];
    const float* noise = (const float*)d_in[1];
    const float* qmat  = (const float*)d_in[2];
    const float* qmw   = (const float*)d_in[3];
    const float* w1    = (const float*)d_in[4];
    const float* b1    = (const float*)d_in[5];
    const float* w2    = (const float*)d_in[6];
    const float* b2    = (const float*)d_in[7];
    const float* w3    = (const float*)d_in[8];
    const float* b3    = (const float*)d_in[9];

    float* out = (float*)d_out;
    int N = out_size / 2;                 // elements per output tensor
    float* lo = out;
    float* hi = out + N;

    prep_kernel<<<1, 32>>>(noise, qmat, qmw, w1, b1, w2, b2, w3, b3);

    // dct_main launched with Programmatic Dependent Launch: it starts while
    // prep_kernel is still running and waits (cudaGridDependencySynchronize)
    // only where the mask is first needed.
    int nblocks8x8 = N / 64;              // 2 lanes per block -> 128 blocks/CTA
    cudaLaunchConfig_t cfg = {};
    cfg.gridDim  = dim3(nblocks8x8 / 128);
    cfg.blockDim = dim3(256);
    cfg.dynamicSmemBytes = 0;
    cfg.stream = 0;
    cudaLaunchAttribute attr[1];
    attr[0].id = cudaLaunchAttributeProgrammaticStreamSerialization;
    attr[0].val.programmaticStreamSerializationAllowed = 1;
    cfg.attrs = attr;
    cfg.numAttrs = 1;
    cudaLaunchKernelEx(&cfg, dct_main, x, lo, hi);
}